// round 5
// baseline (speedup 1.0000x reference)
#include <cuda_runtime.h>

#define NN      262144          // 64^3
#define NNZ_TOT (7 * NN)
#define BS      128
#define CH      32              // batch chunk width
#define NCHUNK  (BS / CH)       // 4

// Scratch (allocation-free rule): per-chunk transposed buffers
__device__ float  g_ypT[(size_t)NN * CH];   // y_pred chunk (N, 32)  32 MB
__device__ float  g_ytT[(size_t)NN * CH];   // y_true chunk (N, 32)  32 MB
__device__ float  g_yhT[(size_t)NN * CH];   // Yhat  chunk (N, 32)  32 MB
__device__ double g_acc[5 * BS];            // s1..s5 per batch element

// ------------------------------------------------------------- zero g_acc
__global__ void zero_acc_kernel() { g_acc[threadIdx.x] = 0.0; }   // 640 thr

// ---- per-chunk prep: transpose yp AND yt chunk, zero yh chunk
// grid = N/32, block = (32, 8)
__global__ void prep_chunk(const float* __restrict__ yp,
                           const float* __restrict__ yt, int b0) {
    __shared__ float tp[32][33];
    __shared__ float tt[32][33];
    int n0 = blockIdx.x * 32;
    int tx = threadIdx.x, ty = threadIdx.y;
#pragma unroll
    for (int r = 0; r < 32; r += 8) {
        size_t src = (size_t)(b0 + ty + r) * NN + n0 + tx;
        tp[ty + r][tx] = __ldcs(yp + src);   // streaming: don't evict resident set
        tt[ty + r][tx] = __ldcs(yt + src);
    }
    // zero Yhat rows for this block (32 n * 32 b = 256 float4)
    int tid = ty * 32 + tx;
    ((float4*)g_yhT)[(size_t)n0 * 8 + tid] = make_float4(0.f, 0.f, 0.f, 0.f);
    __syncthreads();
#pragma unroll
    for (int r = 0; r < 32; r += 8) {
        size_t dst = (size_t)(n0 + ty + r) * 32 + tx;
        g_ypT[dst] = tp[tx][ty + r];
        g_ytT[dst] = tt[tx][ty + r];
    }
}

// ---- per-chunk scatter: Yhat_c[:, r] += v * yp_c[:, c]   (R2, at L2 cap)
__global__ void scatter_chunk(const float* __restrict__ vals,
                              const int* __restrict__ rows,
                              const int* __restrict__ cols) {
    const float4* yp4 = (const float4*)g_ypT;
    float4*       yh4 = (float4*)g_yhT;
    int gid    = blockIdx.x * blockDim.x + threadIdx.x;
    int stride = gridDim.x * blockDim.x;
    int sub    = gid & 7;
    for (int q = gid >> 3; q < NNZ_TOT; q += (stride >> 3)) {
        int   r = __ldcs(rows + q);          // one-pass streams: evict-first
        int   c = __ldcs(cols + q);
        float v = __ldcs(vals + q);
        float4 p = __ldg(&yp4[(size_t)c * 8 + sub]);
        atomicAdd(&yh4[(size_t)r * 8 + sub],
                  make_float4(v * p.x, v * p.y, v * p.z, v * p.w));
    }
}

// ---- per-chunk reduce: s1..s5, all operands in (N,32) L2-resident layout.
// float4 loads: warp covers 4 rows / iter. Thread's batch lanes are fixed:
// j0 = (lane&7)*4. smem only 5KB -> high occupancy.
__global__ void reduce_chunk(int b0) {
    int tid  = threadIdx.x;                   // 256 = 8 warps
    int lane = tid & 31;
    int w    = tid >> 5;
    int gw   = blockIdx.x * 8 + w;            // global warp id
    int nw   = gridDim.x * 8;
    const float4* yp4 = (const float4*)g_ypT;
    const float4* yt4 = (const float4*)g_ytT;
    const float4* yh4 = (const float4*)g_yhT;

    float a1[4] = {0, 0, 0, 0}, a2[4] = {0, 0, 0, 0}, a3[4] = {0, 0, 0, 0};
    float a4[4] = {0, 0, 0, 0}, a5[4] = {0, 0, 0, 0};

    // row-groups of 4 rows: float4 index = rg*32 + lane
#pragma unroll 2
    for (int rg = gw; rg < NN / 4; rg += nw) {
        size_t f = (size_t)rg * 32 + lane;
        float4 p = __ldcs(&yp4[f]);
        float4 t = __ldcs(&yt4[f]);
        float4 h = __ldcs(&yh4[f]);
        a1[0] += t.x * p.x; a1[1] += t.y * p.y; a1[2] += t.z * p.z; a1[3] += t.w * p.w;
        a2[0] += p.x * h.x; a2[1] += p.y * h.y; a2[2] += p.z * h.z; a2[3] += p.w * h.w;
        a3[0] += t.x * t.x; a3[1] += t.y * t.y; a3[2] += t.z * t.z; a3[3] += t.w * t.w;
        a4[0] += t.x * h.x; a4[1] += t.y * h.y; a4[2] += t.z * h.z; a4[3] += t.w * h.w;
        a5[0] += h.x * h.x; a5[1] += h.y * h.y; a5[2] += h.z * h.z; a5[3] += h.w * h.w;
        // Dead lines: this warp is their only reader. Discard to kill
        // dirty-writeback (buffers fully rewritten by next prep_chunk).
        if ((lane & 7) == 0) {
            asm volatile("discard.global.L2 [%0], 128;" :: "l"(&yp4[f]));
            asm volatile("discard.global.L2 [%0], 128;" :: "l"(&yt4[f]));
            asm volatile("discard.global.L2 [%0], 128;" :: "l"(&yh4[f]));
        }
    }

    // intra-warp: sum lanes {l, l+8, l+16, l+24} -> lanes 0..7 own j0..j0+3
#pragma unroll
    for (int k = 0; k < 4; k++) {
#pragma unroll
        for (int d = 16; d >= 8; d >>= 1) {
            a1[k] += __shfl_down_sync(0xffffffffu, a1[k], d);
            a2[k] += __shfl_down_sync(0xffffffffu, a2[k], d);
            a3[k] += __shfl_down_sync(0xffffffffu, a3[k], d);
            a4[k] += __shfl_down_sync(0xffffffffu, a4[k], d);
            a5[k] += __shfl_down_sync(0xffffffffu, a5[k], d);
        }
    }

    __shared__ float red[5][8][32];
    if (lane < 8) {
#pragma unroll
        for (int k = 0; k < 4; k++) {
            red[0][w][lane * 4 + k] = a1[k];
            red[1][w][lane * 4 + k] = a2[k];
            red[2][w][lane * 4 + k] = a3[k];
            red[3][w][lane * 4 + k] = a4[k];
            red[4][w][lane * 4 + k] = a5[k];
        }
    }
    __syncthreads();

    if (tid < 160) {
        int acc = tid >> 5;
        int j   = tid & 31;
        float s = 0.f;
#pragma unroll
        for (int ww = 0; ww < 8; ww++) s += red[acc][ww][j];
        atomicAdd(&g_acc[acc * BS + b0 + j], (double)s);
    }
}

// ------------------------------------------------------------ final scalar
__global__ void final_kernel(float* out) {
    int b = threadIdx.x;            // 128 threads
    double s1 = g_acc[0 * BS + b];
    double s2 = g_acc[1 * BS + b];
    double s3 = g_acc[2 * BS + b];
    double s4 = g_acc[3 * BS + b];
    double s5 = g_acc[4 * BS + b];
    double c  = s1 / s2;
    double r  = s3 - 2.0 * c * s4 + c * c * s5;
    __shared__ double sh[128];
    sh[b] = r;
    __syncthreads();
    for (int s = 64; s > 0; s >>= 1) {
        if (b < s) sh[b] += sh[b + s];
        __syncthreads();
    }
    if (b == 0) out[0] = (float)(sh[0] / (double)BS);
}

extern "C" void kernel_launch(void* const* d_in, const int* in_sizes, int n_in,
                              void* d_out, int out_size) {
    const float* yp   = (const float*)d_in[0];
    const float* yt   = (const float*)d_in[1];
    const float* vals = (const float*)d_in[2];
    const int*   rows = (const int*)d_in[3];
    const int*   cols = (const int*)d_in[4];
    float*       out  = (float*)d_out;

    zero_acc_kernel<<<1, 5 * BS>>>();
    for (int c = 0; c < NCHUNK; c++) {
        int b0 = c * CH;
        prep_chunk<<<NN / 32, dim3(32, 8)>>>(yp, yt, b0);
        scatter_chunk<<<2368, 256>>>(vals, rows, cols);
        reduce_chunk<<<1184, 256>>>(b0);
    }
    final_kernel<<<1, BS>>>(out);
}

// round 6
// speedup vs baseline: 2.0794x; 2.0794x over previous
#include <cuda_runtime.h>

#define NN      262144          // 64^3
#define NNZ_TOT (7 * NN)
#define BS      128
#define CH      32              // batch chunk width
#define NCHUNK  (BS / CH)       // 4

// Scratch (allocation-free rule): per-chunk transposed buffers
__device__ float  g_ypT[(size_t)NN * CH];   // y_pred chunk (N, 32)  32 MB
__device__ float  g_ytT[(size_t)NN * CH];   // y_true chunk (N, 32)  32 MB
__device__ float  g_yhT[(size_t)NN * CH];   // Yhat  chunk (N, 32)  32 MB
__device__ double g_acc[5 * BS];            // s1..s5 per batch element

// ------------------------------------------------------------- zero g_acc
__global__ void zero_acc_kernel() { g_acc[threadIdx.x] = 0.0; }   // 640 thr

// ---- per-chunk prep: transpose yp AND yt chunk, zero yh chunk
// grid = N/32, block = (32, 8)
__global__ void prep_chunk(const float* __restrict__ yp,
                           const float* __restrict__ yt, int b0) {
    __shared__ float tp[32][33];
    __shared__ float tt[32][33];
    int n0 = blockIdx.x * 32;
    int tx = threadIdx.x, ty = threadIdx.y;
#pragma unroll
    for (int r = 0; r < 32; r += 8) {
        size_t src = (size_t)(b0 + ty + r) * NN + n0 + tx;
        tp[ty + r][tx] = yp[src];
        tt[ty + r][tx] = yt[src];
    }
    // zero Yhat rows for this block (32 n * 32 b = 256 float4)
    int tid = ty * 32 + tx;
    ((float4*)g_yhT)[(size_t)n0 * 8 + tid] = make_float4(0.f, 0.f, 0.f, 0.f);
    __syncthreads();
#pragma unroll
    for (int r = 0; r < 32; r += 8) {
        size_t dst = (size_t)(n0 + ty + r) * 32 + tx;
        g_ypT[dst] = tp[tx][ty + r];
        g_ytT[dst] = tt[tx][ty + r];
    }
}

// ---- per-chunk scatter: Yhat_c[:, r] += v * yp_c[:, c]   (R2, at L2 cap)
__global__ void scatter_chunk(const float* __restrict__ vals,
                              const int* __restrict__ rows,
                              const int* __restrict__ cols) {
    const float4* yp4 = (const float4*)g_ypT;
    float4*       yh4 = (float4*)g_yhT;
    int gid    = blockIdx.x * blockDim.x + threadIdx.x;
    int stride = gridDim.x * blockDim.x;
    int sub    = gid & 7;
    for (int q = gid >> 3; q < NNZ_TOT; q += (stride >> 3)) {
        int   r = __ldg(rows + q);
        int   c = __ldg(cols + q);
        float v = __ldg(vals + q);
        float4 p = __ldg(&yp4[(size_t)c * 8 + sub]);
        atomicAdd(&yh4[(size_t)r * 8 + sub],
                  make_float4(v * p.x, v * p.y, v * p.z, v * p.w));
    }
}

// ---- per-chunk reduce: s1..s5, all operands in (N,32) L2-resident layout.
// Plain __ldg float4 loads; warp covers 4 rows / iter; no cache hints.
__global__ void reduce_chunk(int b0) {
    int tid  = threadIdx.x;                   // 256 = 8 warps
    int lane = tid & 31;
    int w    = tid >> 5;
    int gw   = blockIdx.x * 8 + w;            // global warp id
    int nw   = gridDim.x * 8;
    const float4* yp4 = (const float4*)g_ypT;
    const float4* yt4 = (const float4*)g_ytT;
    const float4* yh4 = (const float4*)g_yhT;

    float a1[4] = {0, 0, 0, 0}, a2[4] = {0, 0, 0, 0}, a3[4] = {0, 0, 0, 0};
    float a4[4] = {0, 0, 0, 0}, a5[4] = {0, 0, 0, 0};

#pragma unroll 4
    for (int rg = gw; rg < NN / 4; rg += nw) {
        size_t f = (size_t)rg * 32 + lane;
        float4 p = __ldg(&yp4[f]);
        float4 t = __ldg(&yt4[f]);
        float4 h = __ldg(&yh4[f]);
        a1[0] += t.x * p.x; a1[1] += t.y * p.y; a1[2] += t.z * p.z; a1[3] += t.w * p.w;
        a2[0] += p.x * h.x; a2[1] += p.y * h.y; a2[2] += p.z * h.z; a2[3] += p.w * h.w;
        a3[0] += t.x * t.x; a3[1] += t.y * t.y; a3[2] += t.z * t.z; a3[3] += t.w * t.w;
        a4[0] += t.x * h.x; a4[1] += t.y * h.y; a4[2] += t.z * h.z; a4[3] += t.w * h.w;
        a5[0] += h.x * h.x; a5[1] += h.y * h.y; a5[2] += h.z * h.z; a5[3] += h.w * h.w;
    }

    // intra-warp: lanes {l, l+8, l+16, l+24} hold the same 4 batch cols
#pragma unroll
    for (int k = 0; k < 4; k++) {
#pragma unroll
        for (int d = 16; d >= 8; d >>= 1) {
            a1[k] += __shfl_down_sync(0xffffffffu, a1[k], d);
            a2[k] += __shfl_down_sync(0xffffffffu, a2[k], d);
            a3[k] += __shfl_down_sync(0xffffffffu, a3[k], d);
            a4[k] += __shfl_down_sync(0xffffffffu, a4[k], d);
            a5[k] += __shfl_down_sync(0xffffffffu, a5[k], d);
        }
    }

    __shared__ float red[5][8][32];
    if (lane < 8) {
#pragma unroll
        for (int k = 0; k < 4; k++) {
            red[0][w][lane * 4 + k] = a1[k];
            red[1][w][lane * 4 + k] = a2[k];
            red[2][w][lane * 4 + k] = a3[k];
            red[3][w][lane * 4 + k] = a4[k];
            red[4][w][lane * 4 + k] = a5[k];
        }
    }
    __syncthreads();

    if (tid < 160) {
        int acc = tid >> 5;
        int j   = tid & 31;
        float s = 0.f;
#pragma unroll
        for (int ww = 0; ww < 8; ww++) s += red[acc][ww][j];
        atomicAdd(&g_acc[acc * BS + b0 + j], (double)s);
    }
}

// ------------------------------------------------------------ final scalar
__global__ void final_kernel(float* out) {
    int b = threadIdx.x;            // 128 threads
    double s1 = g_acc[0 * BS + b];
    double s2 = g_acc[1 * BS + b];
    double s3 = g_acc[2 * BS + b];
    double s4 = g_acc[3 * BS + b];
    double s5 = g_acc[4 * BS + b];
    double c  = s1 / s2;
    double r  = s3 - 2.0 * c * s4 + c * c * s5;
    __shared__ double sh[128];
    sh[b] = r;
    __syncthreads();
    for (int s = 64; s > 0; s >>= 1) {
        if (b < s) sh[b] += sh[b + s];
        __syncthreads();
    }
    if (b == 0) out[0] = (float)(sh[0] / (double)BS);
}

extern "C" void kernel_launch(void* const* d_in, const int* in_sizes, int n_in,
                              void* d_out, int out_size) {
    const float* yp   = (const float*)d_in[0];
    const float* yt   = (const float*)d_in[1];
    const float* vals = (const float*)d_in[2];
    const int*   rows = (const int*)d_in[3];
    const int*   cols = (const int*)d_in[4];
    float*       out  = (float*)d_out;

    zero_acc_kernel<<<1, 5 * BS>>>();
    for (int c = 0; c < NCHUNK; c++) {
        int b0 = c * CH;
        prep_chunk<<<NN / 32, dim3(32, 8)>>>(yp, yt, b0);
        scatter_chunk<<<2368, 256>>>(vals, rows, cols);
        reduce_chunk<<<1184, 256>>>(b0);
    }
    final_kernel<<<1, BS>>>(out);
}

// round 7
// speedup vs baseline: 2.3099x; 1.1108x over previous
#include <cuda_runtime.h>

#define NN      262144          // 64^3
#define NNZ_TOT (7 * NN)
#define BS      128
#define CH      32              // batch chunk width
#define NCHUNK  (BS / CH)       // 4

// Resident scratch: ypT + yhT = 64 MB, fits L2 with slack.
__device__ float  g_ypT[(size_t)NN * CH];   // y_pred chunk (N, 32)  32 MB
__device__ float  g_yhT[(size_t)NN * CH];   // Yhat  chunk (N, 32)  32 MB
__device__ double g_acc[5 * BS];            // s1..s5 per batch element

// ------------------------------------------------------------- zero g_acc
__global__ void zero_acc_kernel() { g_acc[threadIdx.x] = 0.0; }   // 640 thr

// ---- per-chunk prep: transpose yp chunk, zero yh chunk (R2 form)
// grid = N/32, block = (32, 8). Source read is one-pass -> __ldcs.
__global__ void prep_chunk(const float* __restrict__ yp, int b0) {
    __shared__ float tp[32][33];
    int n0 = blockIdx.x * 32;
    int tx = threadIdx.x, ty = threadIdx.y;
#pragma unroll
    for (int r = 0; r < 32; r += 8)
        tp[ty + r][tx] = __ldcs(yp + (size_t)(b0 + ty + r) * NN + n0 + tx);
    // zero Yhat rows for this block (32 n * 32 b = 256 float4)
    int tid = ty * 32 + tx;
    ((float4*)g_yhT)[(size_t)n0 * 8 + tid] = make_float4(0.f, 0.f, 0.f, 0.f);
    __syncthreads();
#pragma unroll
    for (int r = 0; r < 32; r += 8)
        g_ypT[(size_t)(n0 + ty + r) * 32 + tx] = tp[tx][ty + r];
}

// ---- per-chunk scatter: Yhat_c[:, r] += v * yp_c[:, c]
// Index streams are one-pass -> __ldcs; resident data -> __ldg.
__global__ void scatter_chunk(const float* __restrict__ vals,
                              const int* __restrict__ rows,
                              const int* __restrict__ cols) {
    const float4* yp4 = (const float4*)g_ypT;
    float4*       yh4 = (float4*)g_yhT;
    int gid    = blockIdx.x * blockDim.x + threadIdx.x;
    int stride = gridDim.x * blockDim.x;
    int sub    = gid & 7;
    for (int q = gid >> 3; q < NNZ_TOT; q += (stride >> 3)) {
        int   r = __ldcs(rows + q);
        int   c = __ldcs(cols + q);
        float v = __ldcs(vals + q);
        float4 p = __ldg(&yp4[(size_t)c * 8 + sub]);
        atomicAdd(&yh4[(size_t)r * 8 + sub],
                  make_float4(v * p.x, v * p.y, v * p.z, v * p.w));
    }
}

// ---- per-chunk reduce: s1..s5. ypT/yhT float4 from L2-resident layout;
// y_true streamed from original layout through a conflict-free smem
// transpose tile (128 n x 32 b). grid = NN/128, block = 256.
__global__ void reduce_chunk(const float* __restrict__ yt, int b0) {
    __shared__ float smT[128][33];     // [n_local][batch j], pad -> no conflicts
    __shared__ float red[5][8][32];
    int tid  = threadIdx.x;            // 256 = 8 warps
    int lane = tid & 31;
    int w    = tid >> 5;
    int nblk = blockIdx.x * 128;       // first n of this block's tile

    // Load yt tile: row j = tid>>3 (0..31), float4 col n4 = pass*8 + (tid&7).
    {
        int j  = tid >> 3;
        int c0 = tid & 7;
        const float4* ytr = (const float4*)(yt + (size_t)(b0 + j) * NN) + blockIdx.x * 32;
#pragma unroll
        for (int pass = 0; pass < 4; pass++) {
            int n4 = pass * 8 + c0;
            float4 v = __ldcs(&ytr[n4]);
            smT[n4 * 4 + 0][j] = v.x;
            smT[n4 * 4 + 1][j] = v.y;
            smT[n4 * 4 + 2][j] = v.z;
            smT[n4 * 4 + 3][j] = v.w;
        }
    }
    __syncthreads();

    const float4* yp4 = (const float4*)g_ypT;
    const float4* yh4 = (const float4*)g_yhT;

    // float4 f = rg*32 + lane covers n = rg*4 + (lane>>3), j0 = (lane&7)*4.
    int j0  = (lane & 7) * 4;
    int nsub = lane >> 3;

    float a1[4] = {0, 0, 0, 0}, a2[4] = {0, 0, 0, 0}, a3[4] = {0, 0, 0, 0};
    float a4[4] = {0, 0, 0, 0}, a5[4] = {0, 0, 0, 0};

#pragma unroll
    for (int k2 = 0; k2 < 4; k2++) {
        int rg_l = w * 4 + k2;                       // local row-group 0..31
        size_t f = ((size_t)blockIdx.x * 32 + rg_l) * 32 + lane;
        float4 p = __ldg(&yp4[f]);
        float4 h = __ldg(&yh4[f]);
        int nl = rg_l * 4 + nsub;
        float t0 = smT[nl][j0 + 0];
        float t1 = smT[nl][j0 + 1];
        float t2 = smT[nl][j0 + 2];
        float t3 = smT[nl][j0 + 3];
        a1[0] += t0 * p.x; a1[1] += t1 * p.y; a1[2] += t2 * p.z; a1[3] += t3 * p.w;
        a2[0] += p.x * h.x; a2[1] += p.y * h.y; a2[2] += p.z * h.z; a2[3] += p.w * h.w;
        a3[0] += t0 * t0;  a3[1] += t1 * t1;  a3[2] += t2 * t2;  a3[3] += t3 * t3;
        a4[0] += t0 * h.x; a4[1] += t1 * h.y; a4[2] += t2 * h.z; a4[3] += t3 * h.w;
        a5[0] += h.x * h.x; a5[1] += h.y * h.y; a5[2] += h.z * h.z; a5[3] += h.w * h.w;
    }

    // lanes {l, l+8, l+16, l+24} hold the same 4 batch columns
#pragma unroll
    for (int k = 0; k < 4; k++) {
#pragma unroll
        for (int d = 16; d >= 8; d >>= 1) {
            a1[k] += __shfl_down_sync(0xffffffffu, a1[k], d);
            a2[k] += __shfl_down_sync(0xffffffffu, a2[k], d);
            a3[k] += __shfl_down_sync(0xffffffffu, a3[k], d);
            a4[k] += __shfl_down_sync(0xffffffffu, a4[k], d);
            a5[k] += __shfl_down_sync(0xffffffffu, a5[k], d);
        }
    }

    if (lane < 8) {
#pragma unroll
        for (int k = 0; k < 4; k++) {
            red[0][w][lane * 4 + k] = a1[k];
            red[1][w][lane * 4 + k] = a2[k];
            red[2][w][lane * 4 + k] = a3[k];
            red[3][w][lane * 4 + k] = a4[k];
            red[4][w][lane * 4 + k] = a5[k];
        }
    }
    __syncthreads();

    if (tid < 160) {
        int acc = tid >> 5;
        int j   = tid & 31;
        float s = 0.f;
#pragma unroll
        for (int ww = 0; ww < 8; ww++) s += red[acc][ww][j];
        atomicAdd(&g_acc[acc * BS + b0 + j], (double)s);
    }
}

// ------------------------------------------------------------ final scalar
__global__ void final_kernel(float* out) {
    int b = threadIdx.x;            // 128 threads
    double s1 = g_acc[0 * BS + b];
    double s2 = g_acc[1 * BS + b];
    double s3 = g_acc[2 * BS + b];
    double s4 = g_acc[3 * BS + b];
    double s5 = g_acc[4 * BS + b];
    double c  = s1 / s2;
    double r  = s3 - 2.0 * c * s4 + c * c * s5;
    __shared__ double sh[128];
    sh[b] = r;
    __syncthreads();
    for (int s = 64; s > 0; s >>= 1) {
        if (b < s) sh[b] += sh[b + s];
        __syncthreads();
    }
    if (b == 0) out[0] = (float)(sh[0] / (double)BS);
}

extern "C" void kernel_launch(void* const* d_in, const int* in_sizes, int n_in,
                              void* d_out, int out_size) {
    const float* yp   = (const float*)d_in[0];
    const float* yt   = (const float*)d_in[1];
    const float* vals = (const float*)d_in[2];
    const int*   rows = (const int*)d_in[3];
    const int*   cols = (const int*)d_in[4];
    float*       out  = (float*)d_out;

    zero_acc_kernel<<<1, 5 * BS>>>();
    for (int c = 0; c < NCHUNK; c++) {
        int b0 = c * CH;
        prep_chunk<<<NN / 32, dim3(32, 8)>>>(yp, b0);
        scatter_chunk<<<2368, 256>>>(vals, rows, cols);
        reduce_chunk<<<NN / 128, 256>>>(yt, b0);
    }
    final_kernel<<<1, BS>>>(out);
}